// round 1
// baseline (speedup 1.0000x reference)
#include <cuda_runtime.h>
#include <cstring>

#define DINLINE __device__ __forceinline__

// ---------- packed fp32x2 helpers (exact fp32 semantics, 2x rate) ----------
DINLINE float2 ffma2(float2 a, float2 b, float2 c) {
    unsigned long long au, bu, cu, ru;
    memcpy(&au, &a, 8); memcpy(&bu, &b, 8); memcpy(&cu, &c, 8);
    asm("fma.rn.f32x2 %0, %1, %2, %3;" : "=l"(ru) : "l"(au), "l"(bu), "l"(cu));
    float2 r; memcpy(&r, &ru, 8); return r;
}
DINLINE float2 fadd2(float2 a, float2 b) {
    unsigned long long au, bu, ru;
    memcpy(&au, &a, 8); memcpy(&bu, &b, 8);
    asm("add.rn.f32x2 %0, %1, %2;" : "=l"(ru) : "l"(au), "l"(bu));
    float2 r; memcpy(&r, &ru, 8); return r;
}
DINLINE float f4get(float4 v, int i) { return i == 0 ? v.x : i == 1 ? v.y : i == 2 ? v.z : v.w; }

// ---------- scratch (static device globals; no allocs) ----------
__device__ unsigned long long g_grid64[32 * 64 * 64];            // 1 MB bitmask: [b][z][y], bit = x
__device__ float g_x1[(size_t)32 * 32 * 32 * 32 * 16];           // 67 MB  [b][z][y][x][c16]
__device__ float g_x2[(size_t)32 * 16 * 16 * 16 * 32];           // 16.8MB [b][z][y][x][c32]
__device__ float g_feat[(size_t)32 * 32768];                     // 4.2 MB [b][c*512 + z*64+y*8+x]

// ---------- kernel 0: clear grid ----------
__global__ void clear_grid() {
    int i = blockIdx.x * 256 + threadIdx.x;            // 65536 threads * 16B = 1MB
    ((ulonglong2*)g_grid64)[i] = make_ulonglong2(0ull, 0ull);
}

// ---------- kernel 1: scatter points into bitmask ----------
__global__ void scatter_kernel(const float* __restrict__ pc) {
    int t = blockIdx.x * 256 + threadIdx.x;            // 524288 = 32*16384
    float px = pc[t * 3 + 0];
    float py = pc[t * 3 + 1];
    float pz = pc[t * 3 + 2];
    int b = t >> 14;
    // exactly mirror ref: ((p + 1.0) * 0.5) * 63, truncate, clamp
    int cx = (int)(((px + 1.0f) * 0.5f) * 63.0f); cx = min(max(cx, 0), 63);
    int cy = (int)(((py + 1.0f) * 0.5f) * 63.0f); cy = min(max(cy, 0), 63);
    int cz = (int)(((pz + 1.0f) * 0.5f) * 63.0f); cz = min(max(cz, 0), 63);
    atomicOr(&g_grid64[(b * 64 + cz) * 64 + cy], 1ull << cx);
}

// ---------- kernel 2: conv1 (1->16, 64^3 -> 32^3), input is binary ----------
__global__ void conv1_kernel(const float* __restrict__ w1, const float* __restrict__ b1) {
    __shared__ float2 sw[27 * 8];   // [tap][cpair]
    __shared__ float2 sb[8];
    int tid = threadIdx.x;
    for (int j = tid; j < 216; j += 256) {
        int cp = j & 7, tap = j >> 3;
        sw[j] = make_float2(w1[(2 * cp) * 27 + tap], w1[(2 * cp + 1) * 27 + tap]);
    }
    if (tid < 8) sb[tid] = make_float2(b1[2 * tid], b1[2 * tid + 1]);
    __syncthreads();

    int idx = blockIdx.x * 256 + tid;                  // 1,048,576 = 32*32^3
    int x = idx & 31, y = (idx >> 5) & 31, z = (idx >> 10) & 31, b = idx >> 15;

    float2 acc[8];
#pragma unroll
    for (int j = 0; j < 8; j++) acc[j] = sb[j];

#pragma unroll 1
    for (int kz = 0; kz < 3; kz++) {
        int iz = 2 * z - 1 + kz;
        if ((unsigned)iz >= 64u) continue;
#pragma unroll 1
        for (int ky = 0; ky < 3; ky++) {
            int iy = 2 * y - 1 + ky;
            if ((unsigned)iy >= 64u) continue;
            unsigned long long m = g_grid64[(b * 64 + iz) * 64 + iy];
            if (!m) continue;
            int tapb = (kz * 3 + ky) * 3;
#pragma unroll 1
            for (int kx = 0; kx < 3; kx++) {
                int ix = 2 * x - 1 + kx;
                if ((unsigned)ix < 64u && ((m >> ix) & 1ull)) {
                    const float2* wv = &sw[(tapb + kx) * 8];
#pragma unroll
                    for (int j = 0; j < 8; j++) acc[j] = fadd2(acc[j], wv[j]);
                }
            }
        }
    }
    float2* outp = (float2*)(g_x1 + (size_t)idx * 16);
#pragma unroll
    for (int j = 0; j < 8; j++) {
        float2 v = acc[j];
        v.x = fmaxf(v.x, 0.0f); v.y = fmaxf(v.y, 0.0f);
        outp[j] = v;
    }
}

// ---------- kernel 3: conv2 (16->32, 32^3 -> 16^3) ----------
// thread = (b, z, y, x0pair): 2 voxels x all 32 out channels (16 float2 accum)
__global__ void conv2_kernel(const float* __restrict__ w2, const float* __restrict__ b2) {
    extern __shared__ float2 dynsm[];                   // 6912 weight float2 + 16 bias
    int tid = threadIdx.x;                              // 128
    for (int j = tid; j < 6912; j += 128) {
        int op = j & 15, i = (j >> 4) & 15, tap = j >> 8;
        dynsm[j] = make_float2(w2[((2 * op) * 16 + i) * 27 + tap],
                               w2[((2 * op + 1) * 16 + i) * 27 + tap]);
    }
    if (tid < 16) dynsm[6912 + tid] = make_float2(b2[2 * tid], b2[2 * tid + 1]);
    __syncthreads();

    int idx = blockIdx.x * 128 + tid;                   // 65536 = 32*16*16*8
    int x0 = (idx & 7) * 2;
    int y = (idx >> 3) & 15, z = (idx >> 7) & 15, b = idx >> 11;

    float2 acc0[16], acc1[16];
#pragma unroll
    for (int op = 0; op < 16; op++) { acc0[op] = dynsm[6912 + op]; acc1[op] = acc0[op]; }

    const float* x1b = g_x1 + (size_t)b * (32 * 32 * 32 * 16);
#pragma unroll 1
    for (int kz = 0; kz < 3; kz++) {
        int iz = 2 * z - 1 + kz;
        if ((unsigned)iz >= 32u) continue;
#pragma unroll 1
        for (int ky = 0; ky < 3; ky++) {
            int iy = 2 * y - 1 + ky;
            if ((unsigned)iy >= 32u) continue;
            const float* rowp = x1b + (size_t)((iz * 32 + iy) * 32) * 16;
#pragma unroll 1
            for (int kx = 0; kx < 3; kx++) {
                int ix0 = 2 * x0 - 1 + kx;              // voxel x0; voxel x0+1 reads ix0+2 (always valid)
                bool v0 = (ix0 >= 0);
                int jx0 = v0 ? ix0 : 0;
                const float4* p0 = (const float4*)(rowp + jx0 * 16);
                const float4* p1 = (const float4*)(rowp + (ix0 + 2) * 16);
                const float4* wr = (const float4*)(dynsm + ((kz * 3 + ky) * 3 + kx) * 256);
#pragma unroll 1
                for (int c4 = 0; c4 < 4; c4++) {
                    float4 A = p0[c4];
                    if (!v0) { A.x = 0.f; A.y = 0.f; A.z = 0.f; A.w = 0.f; }
                    float4 B = p1[c4];
#pragma unroll
                    for (int ii = 0; ii < 4; ii++) {
                        float a0 = f4get(A, ii), a1 = f4get(B, ii);
                        float2 av0 = make_float2(a0, a0);
                        float2 av1 = make_float2(a1, a1);
                        const float4* wi = wr + (c4 * 4 + ii) * 8;
#pragma unroll
                        for (int oq = 0; oq < 8; oq++) {
                            float4 wq = wi[oq];
                            float2 wlo = make_float2(wq.x, wq.y);
                            float2 whi = make_float2(wq.z, wq.w);
                            acc0[2 * oq]     = ffma2(av0, wlo, acc0[2 * oq]);
                            acc0[2 * oq + 1] = ffma2(av0, whi, acc0[2 * oq + 1]);
                            acc1[2 * oq]     = ffma2(av1, wlo, acc1[2 * oq]);
                            acc1[2 * oq + 1] = ffma2(av1, whi, acc1[2 * oq + 1]);
                        }
                    }
                }
            }
        }
    }
    float2* o0p = (float2*)(g_x2 + ((((size_t)b * 16 + z) * 16 + y) * 16 + x0) * 32);
    float2* o1p = o0p + 16;   // next voxel (x0+1): +32 floats
#pragma unroll
    for (int op = 0; op < 16; op++) {
        float2 v = acc0[op];
        v.x = fmaxf(v.x, 0.f); v.y = fmaxf(v.y, 0.f);
        o0p[op] = v;
        v = acc1[op];
        v.x = fmaxf(v.x, 0.f); v.y = fmaxf(v.y, 0.f);
        o1p[op] = v;
    }
}

// ---------- kernel 4: conv3 (32->64, 16^3 -> 8^3), writes flattened feat ----------
// block = (b, oh, chunk); thread = 2 voxels x 32 out channels (half of 64, per oh)
__global__ void conv3_kernel(const float* __restrict__ w3, const float* __restrict__ b3) {
    extern __shared__ float2 dynsm[];                   // 13824 weight float2 + 16 bias
    int tid = threadIdx.x;                              // 128
    int bid = blockIdx.x;                               // 128 = 32b * 2oh * 2chunk
    int chunk = bid & 1, oh = (bid >> 1) & 1, b = bid >> 2;

    for (int j = tid; j < 13824; j += 128) {
        int op = j & 15, i = (j >> 4) & 31, tap = j >> 9;
        int o0 = oh * 32 + 2 * op;
        dynsm[j] = make_float2(w3[(o0 * 32 + i) * 27 + tap],
                               w3[((o0 + 1) * 32 + i) * 27 + tap]);
    }
    if (tid < 16) dynsm[13824 + tid] = make_float2(b3[oh * 32 + 2 * tid], b3[oh * 32 + 2 * tid + 1]);
    __syncthreads();

    int pos = chunk * 128 + tid;                        // 0..255
    int x0 = (pos & 3) * 2;
    int y = (pos >> 2) & 7, z = (pos >> 5) & 7;

    float2 acc0[16], acc1[16];
#pragma unroll
    for (int op = 0; op < 16; op++) { acc0[op] = dynsm[13824 + op]; acc1[op] = acc0[op]; }

    const float* x2b = g_x2 + (size_t)b * (16 * 16 * 16 * 32);
#pragma unroll 1
    for (int kz = 0; kz < 3; kz++) {
        int iz = 2 * z - 1 + kz;
        if ((unsigned)iz >= 16u) continue;
#pragma unroll 1
        for (int ky = 0; ky < 3; ky++) {
            int iy = 2 * y - 1 + ky;
            if ((unsigned)iy >= 16u) continue;
            const float* rowp = x2b + (size_t)((iz * 16 + iy) * 16) * 32;
#pragma unroll 1
            for (int kx = 0; kx < 3; kx++) {
                int ix0 = 2 * x0 - 1 + kx;
                bool v0 = (ix0 >= 0);
                int jx0 = v0 ? ix0 : 0;
                const float4* p0 = (const float4*)(rowp + jx0 * 32);
                const float4* p1 = (const float4*)(rowp + (ix0 + 2) * 32);
                const float4* wr = (const float4*)(dynsm + ((kz * 3 + ky) * 3 + kx) * 512);
#pragma unroll 1
                for (int c4 = 0; c4 < 8; c4++) {
                    float4 A = p0[c4];
                    if (!v0) { A.x = 0.f; A.y = 0.f; A.z = 0.f; A.w = 0.f; }
                    float4 B = p1[c4];
#pragma unroll
                    for (int ii = 0; ii < 4; ii++) {
                        float a0 = f4get(A, ii), a1 = f4get(B, ii);
                        float2 av0 = make_float2(a0, a0);
                        float2 av1 = make_float2(a1, a1);
                        const float4* wi = wr + (c4 * 4 + ii) * 8;
#pragma unroll
                        for (int oq = 0; oq < 8; oq++) {
                            float4 wq = wi[oq];
                            float2 wlo = make_float2(wq.x, wq.y);
                            float2 whi = make_float2(wq.z, wq.w);
                            acc0[2 * oq]     = ffma2(av0, wlo, acc0[2 * oq]);
                            acc0[2 * oq + 1] = ffma2(av0, whi, acc0[2 * oq + 1]);
                            acc1[2 * oq]     = ffma2(av1, wlo, acc1[2 * oq]);
                            acc1[2 * oq + 1] = ffma2(av1, whi, acc1[2 * oq + 1]);
                        }
                    }
                }
            }
        }
    }
    // write relu'd results into flattened feat layout: feat[b][c*512 + s]
    int s0 = z * 64 + y * 8 + x0;                       // even -> float2-aligned
    float* fbase = g_feat + (size_t)b * 32768;
#pragma unroll
    for (int op = 0; op < 16; op++) {
        int c0 = oh * 32 + 2 * op;
        float2 va = acc0[op], vb = acc1[op];
        va.x = fmaxf(va.x, 0.f); va.y = fmaxf(va.y, 0.f);
        vb.x = fmaxf(vb.x, 0.f); vb.y = fmaxf(vb.y, 0.f);
        *(float2*)(fbase + (size_t)c0 * 512 + s0)       = make_float2(va.x, vb.x);
        *(float2*)(fbase + (size_t)(c0 + 1) * 512 + s0) = make_float2(va.y, vb.y);
    }
}

// ---------- kernel 5: FC (32 x 128 <- 32768) ----------
// grid (8 bgroups, 16 lchunks), block 512: thread = (b_local, f_lane), 8 l outputs
__global__ void fc_kernel(const float* __restrict__ fcw, const float* __restrict__ fcb,
                          float* __restrict__ out) {
    int t = threadIdx.x;                                // 512
    int bg = blockIdx.x;                                // 8
    int lc = blockIdx.y;                                // 16
    int bl = t >> 7;                                    // 0..3
    int b = bg * 4 + bl;
    int fl = t & 127;
    int l0 = lc * 8;

    float p[8] = {0.f, 0.f, 0.f, 0.f, 0.f, 0.f, 0.f, 0.f};
    const float4* fv = (const float4*)(g_feat + (size_t)b * 32768);
#pragma unroll 1
    for (int k = fl; k < 8192; k += 128) {
        float4 a = fv[k];
#pragma unroll
        for (int j = 0; j < 8; j++) {
            float4 w = ((const float4*)(fcw + (size_t)(l0 + j) * 32768))[k];
            p[j] += a.x * w.x + a.y * w.y + a.z * w.z + a.w * w.w;
        }
    }
    // warp reduce (all lanes in a warp share the same b)
#pragma unroll
    for (int j = 0; j < 8; j++) {
        float v = p[j];
        for (int off = 16; off > 0; off >>= 1) v += __shfl_xor_sync(0xffffffffu, v, off);
        p[j] = v;
    }
    __shared__ float sh[16][8];
    int warp = t >> 5, lane = t & 31;
    if (lane == 0) {
#pragma unroll
        for (int j = 0; j < 8; j++) sh[warp][j] = p[j];
    }
    __syncthreads();
    if (t < 32) {
        int blb = t >> 3, j = t & 7;
        float s = sh[blb * 4 + 0][j] + sh[blb * 4 + 1][j] + sh[blb * 4 + 2][j] + sh[blb * 4 + 3][j];
        out[(size_t)(bg * 4 + blb) * 128 + l0 + j] = s + fcb[l0 + j];
    }
}

// ---------- launch ----------
extern "C" void kernel_launch(void* const* d_in, const int* in_sizes, int n_in,
                              void* d_out, int out_size) {
    (void)in_sizes; (void)n_in; (void)out_size;
    const float* pc  = (const float*)d_in[0];
    const float* w1  = (const float*)d_in[1];
    const float* b1  = (const float*)d_in[2];
    const float* w2  = (const float*)d_in[3];
    const float* b2  = (const float*)d_in[4];
    const float* w3  = (const float*)d_in[5];
    const float* b3  = (const float*)d_in[6];
    const float* fcw = (const float*)d_in[7];
    const float* fcb = (const float*)d_in[8];
    float* out = (float*)d_out;

    cudaFuncSetAttribute(conv2_kernel, cudaFuncAttributeMaxDynamicSharedMemorySize, 55424);
    cudaFuncSetAttribute(conv3_kernel, cudaFuncAttributeMaxDynamicSharedMemorySize, 110720);

    clear_grid<<<256, 256>>>();
    scatter_kernel<<<2048, 256>>>(pc);
    conv1_kernel<<<4096, 256>>>(w1, b1);
    conv2_kernel<<<512, 128, 55424>>>(w2, b2);
    conv3_kernel<<<128, 128, 110720>>>(w3, b3);
    fc_kernel<<<dim3(8, 16), 512>>>(fcw, fcb, out);
}